// round 2
// baseline (speedup 1.0000x reference)
#include <cuda_runtime.h>
#include <math.h>

#define BB 128
#define TT 256
#define FF 64
#define HH 512
#define G4 2048   // 4*H

// ---------------- scratch (device globals; no allocation) ----------------
__device__ float g_h[BB * TT * HH];     // dense1+norm output  [B,T,H]
__device__ float g_seq[BB * TT * HH];   // LSTM1 sequence out  [B,T,H]
__device__ float g_xg[BB * TT * G4];    // precomputed input gates [B,T,4H]
__device__ float g_hA[BB * HH], g_hB[BB * HH];
__device__ float g_cA[BB * HH], g_cB[BB * HH];
__device__ float g_ln[BB * HH];         // layernorm output [B,H]
__device__ float g_d2[BB * (HH / 2)];   // dense2 output [B,256]

// ---------------- dense1 + spectral-norm scale ----------------
// block: 16 rows of (B*T), 256 threads; each thread 2 cols x 16 rows
__global__ void dense1_norm(const float* __restrict__ x,
                            const float* __restrict__ W1,
                            const float* __restrict__ b1) {
    __shared__ float xs[16][FF];
    __shared__ float hs[16][HH];   // 32KB
    const int tid = threadIdx.x;
    const int m0 = blockIdx.x * 16;

    for (int i = tid; i < 16 * FF; i += 256) {
        int r = i / FF, k = i % FF;
        xs[r][k] = x[(m0 + r) * FF + k];
    }
    __syncthreads();

    const int c0 = tid * 2;
    float acc0[16], acc1[16];
#pragma unroll
    for (int r = 0; r < 16; r++) { acc0[r] = 0.f; acc1[r] = 0.f; }

    for (int k = 0; k < FF; k++) {
        float w0 = W1[k * HH + c0];
        float w1 = W1[k * HH + c0 + 1];
#pragma unroll
        for (int r = 0; r < 16; r++) {
            float xv = xs[r][k];
            acc0[r] += xv * w0;
            acc1[r] += xv * w1;
        }
    }
    float bb0 = b1[c0], bb1 = b1[c0 + 1];
#pragma unroll
    for (int r = 0; r < 16; r++) {
        hs[r][c0]     = acc0[r] + bb0;
        hs[r][c0 + 1] = acc1[r] + bb1;
    }
    __syncthreads();

    // per-row L2 norm, scale by sqrt(H); 8 warps * 2 rows
    int wid = tid >> 5, lane = tid & 31;
#pragma unroll
    for (int rr = 0; rr < 2; rr++) {
        int r = wid * 2 + rr;
        float ss = 0.f;
        for (int c = lane; c < HH; c += 32) { float v = hs[r][c]; ss += v * v; }
#pragma unroll
        for (int o = 16; o; o >>= 1) ss += __shfl_xor_sync(0xffffffffu, ss, o);
        float scale = sqrtf((float)HH) / fmaxf(sqrtf(ss), 1e-12f);
        for (int c = lane; c < HH; c += 32)
            g_h[(m0 + r) * HH + c] = hs[r][c] * scale;
    }
}

// ---------------- xg GEMM: C[M,2048] = A[M,512] @ Wx + bias ----------------
// 64x64 tile, 256 threads, 4x4 per-thread register tile, Kc=16
__global__ void gemm_xg(int src, const float* __restrict__ Wx,
                        const float* __restrict__ bias) {
    const float* __restrict__ A = src ? g_seq : g_h;
    __shared__ float As[16][64];  // A^T tile [k][m]
    __shared__ float Bs[16][64];
    const int tid = threadIdx.x;
    const int tx = tid & 15, ty = tid >> 4;
    const int n0 = blockIdx.x * 64;
    const int m0 = blockIdx.y * 64;

    float acc[4][4] = {};

    for (int kc = 0; kc < HH; kc += 16) {
        for (int i = tid; i < 1024; i += 256) {
            int m = i >> 4, k = i & 15;
            As[k][m] = A[(m0 + m) * HH + kc + k];
        }
        for (int i = tid; i < 1024; i += 256) {
            int k = i >> 6, n = i & 63;
            Bs[k][n] = Wx[(kc + k) * G4 + n0 + n];
        }
        __syncthreads();
#pragma unroll
        for (int k = 0; k < 16; k++) {
            float4 a = *(const float4*)&As[k][ty * 4];
            float4 b = *(const float4*)&Bs[k][tx * 4];
            acc[0][0] += a.x * b.x; acc[0][1] += a.x * b.y; acc[0][2] += a.x * b.z; acc[0][3] += a.x * b.w;
            acc[1][0] += a.y * b.x; acc[1][1] += a.y * b.y; acc[1][2] += a.y * b.z; acc[1][3] += a.y * b.w;
            acc[2][0] += a.z * b.x; acc[2][1] += a.z * b.y; acc[2][2] += a.z * b.z; acc[2][3] += a.z * b.w;
            acc[3][0] += a.w * b.x; acc[3][1] += a.w * b.y; acc[3][2] += a.w * b.z; acc[3][3] += a.w * b.w;
        }
        __syncthreads();
    }
#pragma unroll
    for (int i = 0; i < 4; i++) {
#pragma unroll
        for (int j = 0; j < 4; j++) {
            int n = n0 + tx * 4 + j;
            g_xg[(m0 + ty * 4 + i) * G4 + n] = acc[i][j] + bias[n];
        }
    }
}

// ---------------- zero initial LSTM state ----------------
__global__ void zero_state() {
    int i = blockIdx.x * 256 + threadIdx.x;
    if (i < BB * HH) { g_hA[i] = 0.f; g_cA[i] = 0.f; }
}

// ---------------- fused LSTM step ----------------
// grid (4, 32): block = 32 batch rows x 16 hidden cols, computes all 4 gates
__global__ void lstm_step(const float* __restrict__ Wh, int t, int flip) {
    const float* __restrict__ h_prev = flip ? g_hB : g_hA;
    const float* __restrict__ c_prev = flip ? g_cB : g_cA;
    float* __restrict__ h_next = flip ? g_hA : g_hB;
    float* __restrict__ c_next = flip ? g_cA : g_cB;

    __shared__ float As[32][33];
    __shared__ float Bs[32][64];
    __shared__ float Gs[32][64];

    const int tid = threadIdx.x;
    const int b0 = blockIdx.x * 32;
    const int j0 = blockIdx.y * 16;

    const int r = tid >> 3;          // 0..31 (batch row within tile)
    const int c0 = (tid & 7) * 8;    // 0..56 (gate-col within 64)

    float acc[8] = {};

    for (int kc = 0; kc < HH; kc += 32) {
        for (int i = tid; i < 32 * 32; i += 256) {
            int rr = i >> 5, k = i & 31;
            As[rr][k] = h_prev[(b0 + rr) * HH + kc + k];
        }
        for (int i = tid; i < 32 * 64; i += 256) {
            int k = i >> 6, c = i & 63;
            int gate = c >> 4;
            Bs[k][c] = Wh[(kc + k) * G4 + gate * HH + j0 + (c & 15)];
        }
        __syncthreads();
#pragma unroll
        for (int k = 0; k < 32; k++) {
            float a = As[r][k];
            float4 p = *(const float4*)&Bs[k][c0];
            float4 q = *(const float4*)&Bs[k][c0 + 4];
            acc[0] += a * p.x; acc[1] += a * p.y; acc[2] += a * p.z; acc[3] += a * p.w;
            acc[4] += a * q.x; acc[5] += a * q.y; acc[6] += a * q.z; acc[7] += a * q.w;
        }
        __syncthreads();
    }
#pragma unroll
    for (int i = 0; i < 8; i++) Gs[r][c0 + i] = acc[i];
    __syncthreads();

    // gate math: 32x16 = 512 elements, 2 per thread
    for (int p = tid; p < 32 * 16; p += 256) {
        int rr = p >> 4, jj = p & 15;
        int b = b0 + rr, j = j0 + jj;
        int xbase = (b * TT + t) * G4;
        float iv = Gs[rr][jj]      + g_xg[xbase + j];
        float fv = Gs[rr][16 + jj] + g_xg[xbase + HH + j];
        float cv = Gs[rr][32 + jj] + g_xg[xbase + 2 * HH + j];
        float ov = Gs[rr][48 + jj] + g_xg[xbase + 3 * HH + j];
        iv = 1.f / (1.f + expf(-iv));
        fv = 1.f / (1.f + expf(-fv));
        ov = 1.f / (1.f + expf(-ov));
        cv = tanhf(cv);
        float c = fv * c_prev[b * HH + j] + iv * cv;
        float h = ov * tanhf(c);
        c_next[b * HH + j] = c;
        h_next[b * HH + j] = h;
        g_seq[(b * TT + t) * HH + j] = h;
    }
}

// ---------------- layernorm (eps=1e-3) on final h (in g_hA) ----------------
__global__ void layernorm(const float* __restrict__ gamma,
                          const float* __restrict__ beta) {
    const int b = blockIdx.x, tid = threadIdx.x;
    const float* __restrict__ h = &g_hA[b * HH];
    __shared__ float red[8];
    __shared__ float bc_mu, bc_rs;

    float s = 0.f;
    for (int j = tid; j < HH; j += 256) s += h[j];
#pragma unroll
    for (int o = 16; o; o >>= 1) s += __shfl_xor_sync(0xffffffffu, s, o);
    if ((tid & 31) == 0) red[tid >> 5] = s;
    __syncthreads();
    if (tid == 0) {
        float tsum = 0.f;
        for (int i = 0; i < 8; i++) tsum += red[i];
        bc_mu = tsum / (float)HH;
    }
    __syncthreads();
    float mu = bc_mu;

    float v = 0.f;
    for (int j = tid; j < HH; j += 256) { float d = h[j] - mu; v += d * d; }
#pragma unroll
    for (int o = 16; o; o >>= 1) v += __shfl_xor_sync(0xffffffffu, v, o);
    __syncthreads();
    if ((tid & 31) == 0) red[tid >> 5] = v;
    __syncthreads();
    if (tid == 0) {
        float tsum = 0.f;
        for (int i = 0; i < 8; i++) tsum += red[i];
        bc_rs = rsqrtf(tsum / (float)HH + 1e-3f);
    }
    __syncthreads();
    float rs = bc_rs;

    for (int j = tid; j < HH; j += 256)
        g_ln[b * HH + j] = (h[j] - mu) * rs * gamma[j] + beta[j];
}

// ---------------- dense2 + relu: [128,512]@[512,256] ----------------
__global__ void dense2(const float* __restrict__ W2, const float* __restrict__ b2) {
    const int b = blockIdx.x, c = threadIdx.x;   // 256 threads
    const float* __restrict__ h = &g_ln[b * HH];
    float s = b2[c];
    for (int k = 0; k < HH; k++) s += h[k] * W2[k * 256 + c];
    g_d2[b * 256 + c] = fmaxf(s, 0.f);
}

// ---------------- dense3: [128,256]@[256,1] ----------------
__global__ void dense3(const float* __restrict__ W3, const float* __restrict__ b3,
                       float* __restrict__ out) {
    const int b = blockIdx.x, tid = threadIdx.x;  // 256 threads
    float s = g_d2[b * 256 + tid] * W3[tid];
#pragma unroll
    for (int o = 16; o; o >>= 1) s += __shfl_xor_sync(0xffffffffu, s, o);
    __shared__ float red[8];
    if ((tid & 31) == 0) red[tid >> 5] = s;
    __syncthreads();
    if (tid == 0) {
        float tsum = 0.f;
        for (int i = 0; i < 8; i++) tsum += red[i];
        out[b] = tsum + b3[0];
    }
}

// ---------------- launch ----------------
extern "C" void kernel_launch(void* const* d_in, const int* in_sizes, int n_in,
                              void* d_out, int out_size) {
    const float* x     = (const float*)d_in[0];
    const float* W1    = (const float*)d_in[1];
    const float* b1    = (const float*)d_in[2];
    const float* Wx1   = (const float*)d_in[3];
    const float* Wh1   = (const float*)d_in[4];
    const float* bl1   = (const float*)d_in[5];
    const float* Wx2   = (const float*)d_in[6];
    const float* Wh2   = (const float*)d_in[7];
    const float* bl2   = (const float*)d_in[8];
    const float* gamma = (const float*)d_in[9];
    const float* beta  = (const float*)d_in[10];
    const float* W2    = (const float*)d_in[11];
    const float* b2    = (const float*)d_in[12];
    const float* W3    = (const float*)d_in[13];
    const float* b3    = (const float*)d_in[14];
    float* out = (float*)d_out;

    // dense1 + L2-norm scale
    dense1_norm<<<(BB * TT) / 16, 256>>>(x, W1, b1);

    // LSTM 1
    gemm_xg<<<dim3(G4 / 64, (BB * TT) / 64), 256>>>(0, Wx1, bl1);
    zero_state<<<(BB * HH + 255) / 256, 256>>>();
    for (int t = 0; t < TT; t++)
        lstm_step<<<dim3(BB / 32, HH / 16), 256>>>(Wh1, t, t & 1);

    // LSTM 2 (input = g_seq)
    gemm_xg<<<dim3(G4 / 64, (BB * TT) / 64), 256>>>(1, Wx2, bl2);
    zero_state<<<(BB * HH + 255) / 256, 256>>>();
    for (int t = 0; t < TT; t++)
        lstm_step<<<dim3(BB / 32, HH / 16), 256>>>(Wh2, t, t & 1);

    // head
    layernorm<<<BB, 256>>>(gamma, beta);
    dense2<<<BB, 256>>>(W2, b2);
    dense3<<<BB, 256>>>(W3, b3, out);
}

// round 3
// speedup vs baseline: 3.2346x; 3.2346x over previous
#include <cuda_runtime.h>
#include <math.h>

#define BB 128
#define TT 256
#define FF 64
#define HH 512
#define G4 2048   // 4*H
#define NBLK 128  // persistent LSTM grid size

// ---------------- scratch (device globals; no allocation) ----------------
__device__ float g_h[BB * TT * HH];     // dense1+norm output  [B,T,H]
__device__ float g_seq[BB * TT * HH];   // LSTM1 sequence out  [B,T,H]
__device__ float g_xg[BB * TT * G4];    // precomputed input gates [B,T,4H]
__device__ float g_hA[BB * HH], g_hB[BB * HH];
__device__ float g_ln[BB * HH];         // layernorm output [B,H]
__device__ float g_d2[BB * (HH / 2)];   // dense2 output [B,256]
__device__ unsigned g_bar_count = 0;
__device__ unsigned g_bar_gen = 0;

// ---------------- software grid barrier (all NBLK blocks co-resident) ----
__device__ __forceinline__ void grid_bar() {
    __syncthreads();
    if (threadIdx.x == 0) {
        __threadfence();
        unsigned gen = *((volatile unsigned*)&g_bar_gen);
        if (atomicAdd(&g_bar_count, 1u) == NBLK - 1) {
            g_bar_count = 0;
            __threadfence();
            atomicAdd(&g_bar_gen, 1u);
        } else {
            while (*((volatile unsigned*)&g_bar_gen) == gen) {}
            __threadfence();
        }
    }
    __syncthreads();
}

// ---------------- dense1 + spectral-norm scale ----------------
__global__ void dense1_norm(const float* __restrict__ x,
                            const float* __restrict__ W1,
                            const float* __restrict__ b1) {
    __shared__ float xs[16][FF];
    __shared__ float hs[16][HH];
    const int tid = threadIdx.x;
    const int m0 = blockIdx.x * 16;

    for (int i = tid; i < 16 * FF; i += 256) {
        int r = i / FF, k = i % FF;
        xs[r][k] = x[(m0 + r) * FF + k];
    }
    __syncthreads();

    const int c0 = tid * 2;
    float acc0[16], acc1[16];
#pragma unroll
    for (int r = 0; r < 16; r++) { acc0[r] = 0.f; acc1[r] = 0.f; }

    for (int k = 0; k < FF; k++) {
        float w0 = W1[k * HH + c0];
        float w1 = W1[k * HH + c0 + 1];
#pragma unroll
        for (int r = 0; r < 16; r++) {
            float xv = xs[r][k];
            acc0[r] += xv * w0;
            acc1[r] += xv * w1;
        }
    }
    float bb0 = b1[c0], bb1 = b1[c0 + 1];
#pragma unroll
    for (int r = 0; r < 16; r++) {
        hs[r][c0]     = acc0[r] + bb0;
        hs[r][c0 + 1] = acc1[r] + bb1;
    }
    __syncthreads();

    int wid = tid >> 5, lane = tid & 31;
#pragma unroll
    for (int rr = 0; rr < 2; rr++) {
        int r = wid * 2 + rr;
        float ss = 0.f;
        for (int c = lane; c < HH; c += 32) { float v = hs[r][c]; ss += v * v; }
#pragma unroll
        for (int o = 16; o; o >>= 1) ss += __shfl_xor_sync(0xffffffffu, ss, o);
        float scale = sqrtf((float)HH) / fmaxf(sqrtf(ss), 1e-12f);
        for (int c = lane; c < HH; c += 32)
            g_h[(m0 + r) * HH + c] = hs[r][c] * scale;
    }
}

// ---------------- xg GEMM: C[M,2048] = A[M,512] @ Wx + bias ----------------
// 128x128 tile, 256 threads, 8x8 per-thread register tile, Kc=16
__global__ void gemm_xg(int src, const float* __restrict__ Wx,
                        const float* __restrict__ bias) {
    const float* __restrict__ A = src ? g_seq : g_h;
    __shared__ float As[16 * 128];  // [k][m]
    __shared__ float Bs[16 * 128];  // [k][n]
    const int tid = threadIdx.x;
    const int tx = tid & 15, ty = tid >> 4;
    const int n0 = blockIdx.x * 128;
    const int m0 = blockIdx.y * 128;

    const int lm = tid >> 1;            // 0..127
    const int lk = (tid & 1) * 8;       // 0 or 8
    const int bn = (tid & 31) * 4;      // 0..124
    const int bk = tid >> 5;            // 0..7

    float acc[8][8];
#pragma unroll
    for (int i = 0; i < 8; i++)
#pragma unroll
        for (int j = 0; j < 8; j++) acc[i][j] = 0.f;

    for (int kc = 0; kc < HH; kc += 16) {
        float4 av0 = *(const float4*)&A[(m0 + lm) * HH + kc + lk];
        float4 av1 = *(const float4*)&A[(m0 + lm) * HH + kc + lk + 4];
        As[(lk + 0) * 128 + lm] = av0.x;
        As[(lk + 1) * 128 + lm] = av0.y;
        As[(lk + 2) * 128 + lm] = av0.z;
        As[(lk + 3) * 128 + lm] = av0.w;
        As[(lk + 4) * 128 + lm] = av1.x;
        As[(lk + 5) * 128 + lm] = av1.y;
        As[(lk + 6) * 128 + lm] = av1.z;
        As[(lk + 7) * 128 + lm] = av1.w;
        *(float4*)&Bs[bk * 128 + bn] =
            *(const float4*)&Wx[(kc + bk) * G4 + n0 + bn];
        *(float4*)&Bs[(bk + 8) * 128 + bn] =
            *(const float4*)&Wx[(kc + bk + 8) * G4 + n0 + bn];
        __syncthreads();
#pragma unroll
        for (int k = 0; k < 16; k++) {
            float4 a0 = *(const float4*)&As[k * 128 + ty * 4];
            float4 a1 = *(const float4*)&As[k * 128 + ty * 4 + 64];
            float4 b0 = *(const float4*)&Bs[k * 128 + tx * 4];
            float4 b1 = *(const float4*)&Bs[k * 128 + tx * 4 + 64];
            float av[8] = {a0.x, a0.y, a0.z, a0.w, a1.x, a1.y, a1.z, a1.w};
            float bv[8] = {b0.x, b0.y, b0.z, b0.w, b1.x, b1.y, b1.z, b1.w};
#pragma unroll
            for (int i = 0; i < 8; i++)
#pragma unroll
                for (int j = 0; j < 8; j++) acc[i][j] += av[i] * bv[j];
        }
        __syncthreads();
    }

    float4 bia0 = *(const float4*)&bias[n0 + tx * 4];
    float4 bia1 = *(const float4*)&bias[n0 + tx * 4 + 64];
#pragma unroll
    for (int i = 0; i < 8; i++) {
        int r = m0 + ty * 4 + (i & 3) + (i >> 2) * 64;
        float4 o0, o1;
        o0.x = acc[i][0] + bia0.x; o0.y = acc[i][1] + bia0.y;
        o0.z = acc[i][2] + bia0.z; o0.w = acc[i][3] + bia0.w;
        o1.x = acc[i][4] + bia1.x; o1.y = acc[i][5] + bia1.y;
        o1.z = acc[i][6] + bia1.z; o1.w = acc[i][7] + bia1.w;
        *(float4*)&g_xg[(size_t)r * G4 + n0 + tx * 4] = o0;
        *(float4*)&g_xg[(size_t)r * G4 + n0 + tx * 4 + 64] = o1;
    }
}

// ---------------- zero initial LSTM hidden state ----------------
__global__ void zero_state() {
    int i = blockIdx.x * 256 + threadIdx.x;
    if (i < BB * HH) g_hA[i] = 0.f;
}

// ---------------- persistent fused LSTM (whole sequence, one launch) -----
// grid (4, 32): block = 32 batch x 16 hidden cols (x4 gates = 64 gate cols)
// Wh slice resident in SMEM; c state resident in SMEM; grid barrier per step.
#define SMEM_LSTM ((512 * 64 + 32 * 512 + 32 * 64 + 32 * 16) * 4)

__global__ void __launch_bounds__(256, 1)
lstm_persist(const float* __restrict__ Wh, int layer) {
    extern __shared__ float sm[];
    float* Whs = sm;                       // [512][64]
    float* As  = Whs + 512 * 64;           // [32][512]
    float* Gs  = As + 32 * 512;            // [32][64]
    float* cs  = Gs + 32 * 64;             // [32][16]

    const int tid = threadIdx.x;
    const int b0 = blockIdx.x * 32;
    const int j0 = blockIdx.y * 16;

    // load Wh slice once: Whs[k][c], c = gate*16 + jj
    for (int i = tid; i < 512 * 64; i += 256) {
        int k = i >> 6, c = i & 63;
        Whs[i] = Wh[k * G4 + (c >> 4) * HH + j0 + (c & 15)];
    }
    for (int i = tid; i < 512; i += 256) cs[i] = 0.f;
    __syncthreads();

    const int c0 = (tid & 15) * 4;      // gate-col within 64
    const int r0 = (tid >> 4) * 2;      // batch row pair within 32

    for (int t = 0; t < TT; t++) {
        const float* __restrict__ hprev = (t & 1) ? g_hB : g_hA;
        float* __restrict__ hnext = (t & 1) ? g_hA : g_hB;

        // load h_prev tile [32][512]
        for (int i = tid * 4; i < 32 * 512; i += 256 * 4)
            *(float4*)&As[i] =
                *(const float4*)&hprev[((b0 + (i >> 9)) << 9) + (i & 511)];
        __syncthreads();

        float acc[2][4] = {{0.f, 0.f, 0.f, 0.f}, {0.f, 0.f, 0.f, 0.f}};
        const float* A0 = &As[r0 * 512];
        const float* A1 = &As[(r0 + 1) * 512];
#pragma unroll 4
        for (int k = 0; k < 512; k++) {
            float a0 = A0[k], a1 = A1[k];
            float4 b = *(const float4*)&Whs[k * 64 + c0];
            acc[0][0] += a0 * b.x; acc[0][1] += a0 * b.y;
            acc[0][2] += a0 * b.z; acc[0][3] += a0 * b.w;
            acc[1][0] += a1 * b.x; acc[1][1] += a1 * b.y;
            acc[1][2] += a1 * b.z; acc[1][3] += a1 * b.w;
        }
        *(float4*)&Gs[r0 * 64 + c0] =
            make_float4(acc[0][0], acc[0][1], acc[0][2], acc[0][3]);
        *(float4*)&Gs[(r0 + 1) * 64 + c0] =
            make_float4(acc[1][0], acc[1][1], acc[1][2], acc[1][3]);
        __syncthreads();

        // gate math: 32x16 elements, 2 per thread
#pragma unroll
        for (int p = tid; p < 512; p += 256) {
            int rr = p >> 4, jj = p & 15;
            int b = b0 + rr, j = j0 + jj;
            const float* __restrict__ xg = &g_xg[(size_t)(b * TT + t) * G4 + j];
            float iv = Gs[rr * 64 + jj]      + xg[0];
            float fv = Gs[rr * 64 + 16 + jj] + xg[512];
            float cv = Gs[rr * 64 + 32 + jj] + xg[1024];
            float ov = Gs[rr * 64 + 48 + jj] + xg[1536];
            iv = 1.f / (1.f + expf(-iv));
            fv = 1.f / (1.f + expf(-fv));
            ov = 1.f / (1.f + expf(-ov));
            cv = tanhf(cv);
            float c = fv * cs[p] + iv * cv;
            cs[p] = c;
            float h = ov * tanhf(c);
            hnext[b * HH + j] = h;
            if (layer == 0) g_seq[(size_t)(b * TT + t) * HH + j] = h;
        }

        if (t < TT - 1) grid_bar();
    }
}

// ---------------- layernorm (eps=1e-3) on final h (in g_hA) ----------------
__global__ void layernorm(const float* __restrict__ gamma,
                          const float* __restrict__ beta) {
    const int b = blockIdx.x, tid = threadIdx.x;
    const float* __restrict__ h = &g_hA[b * HH];
    __shared__ float red[8];
    __shared__ float bc_mu, bc_rs;

    float s = 0.f;
    for (int j = tid; j < HH; j += 256) s += h[j];
#pragma unroll
    for (int o = 16; o; o >>= 1) s += __shfl_xor_sync(0xffffffffu, s, o);
    if ((tid & 31) == 0) red[tid >> 5] = s;
    __syncthreads();
    if (tid == 0) {
        float tsum = 0.f;
        for (int i = 0; i < 8; i++) tsum += red[i];
        bc_mu = tsum / (float)HH;
    }
    __syncthreads();
    float mu = bc_mu;

    float v = 0.f;
    for (int j = tid; j < HH; j += 256) { float d = h[j] - mu; v += d * d; }
#pragma unroll
    for (int o = 16; o; o >>= 1) v += __shfl_xor_sync(0xffffffffu, v, o);
    __syncthreads();
    if ((tid & 31) == 0) red[tid >> 5] = v;
    __syncthreads();
    if (tid == 0) {
        float tsum = 0.f;
        for (int i = 0; i < 8; i++) tsum += red[i];
        bc_rs = rsqrtf(tsum / (float)HH + 1e-3f);
    }
    __syncthreads();
    float rs = bc_rs;

    for (int j = tid; j < HH; j += 256)
        g_ln[b * HH + j] = (h[j] - mu) * rs * gamma[j] + beta[j];
}

// ---------------- dense2 + relu ----------------
__global__ void dense2(const float* __restrict__ W2, const float* __restrict__ b2) {
    const int b = blockIdx.x, c = threadIdx.x;
    const float* __restrict__ h = &g_ln[b * HH];
    float s = b2[c];
    for (int k = 0; k < HH; k++) s += h[k] * W2[k * 256 + c];
    g_d2[b * 256 + c] = fmaxf(s, 0.f);
}

// ---------------- dense3 ----------------
__global__ void dense3(const float* __restrict__ W3, const float* __restrict__ b3,
                       float* __restrict__ out) {
    const int b = blockIdx.x, tid = threadIdx.x;
    float s = g_d2[b * 256 + tid] * W3[tid];
#pragma unroll
    for (int o = 16; o; o >>= 1) s += __shfl_xor_sync(0xffffffffu, s, o);
    __shared__ float red[8];
    if ((tid & 31) == 0) red[tid >> 5] = s;
    __syncthreads();
    if (tid == 0) {
        float tsum = 0.f;
        for (int i = 0; i < 8; i++) tsum += red[i];
        out[b] = tsum + b3[0];
    }
}

// ---------------- launch ----------------
extern "C" void kernel_launch(void* const* d_in, const int* in_sizes, int n_in,
                              void* d_out, int out_size) {
    const float* x     = (const float*)d_in[0];
    const float* W1    = (const float*)d_in[1];
    const float* b1    = (const float*)d_in[2];
    const float* Wx1   = (const float*)d_in[3];
    const float* Wh1   = (const float*)d_in[4];
    const float* bl1   = (const float*)d_in[5];
    const float* Wx2   = (const float*)d_in[6];
    const float* Wh2   = (const float*)d_in[7];
    const float* bl2   = (const float*)d_in[8];
    const float* gamma = (const float*)d_in[9];
    const float* beta  = (const float*)d_in[10];
    const float* W2    = (const float*)d_in[11];
    const float* b2    = (const float*)d_in[12];
    const float* W3    = (const float*)d_in[13];
    const float* b3    = (const float*)d_in[14];
    float* out = (float*)d_out;

    static int smem_set = 0;
    if (!smem_set) {
        cudaFuncSetAttribute(lstm_persist,
                             cudaFuncAttributeMaxDynamicSharedMemorySize,
                             SMEM_LSTM);
        smem_set = 1;
    }

    dense1_norm<<<(BB * TT) / 16, 256>>>(x, W1, b1);

    gemm_xg<<<dim3(G4 / 128, (BB * TT) / 128), 256>>>(0, Wx1, bl1);
    zero_state<<<(BB * HH + 255) / 256, 256>>>();
    lstm_persist<<<dim3(4, 32), 256, SMEM_LSTM>>>(Wh1, 0);

    gemm_xg<<<dim3(G4 / 128, (BB * TT) / 128), 256>>>(1, Wx2, bl2);
    zero_state<<<(BB * HH + 255) / 256, 256>>>();
    lstm_persist<<<dim3(4, 32), 256, SMEM_LSTM>>>(Wh2, 1);

    layernorm<<<BB, 256>>>(gamma, beta);
    dense2<<<BB, 256>>>(W2, b2);
    dense3<<<BB, 256>>>(W3, b3, out);
}

// round 4
// speedup vs baseline: 3.6853x; 1.1393x over previous
#include <cuda_runtime.h>
#include <math.h>

#define BB 128
#define TT 256
#define FF 64
#define HH 512
#define G4 2048   // 4*H
#define NBLK 128  // persistent LSTM grid size

// ---------------- packed f32x2 helpers (sm_100+) ----------------
__device__ __forceinline__ unsigned long long pack2(float x, float y) {
    unsigned long long r;
    asm("mov.b64 %0, {%1, %2};"
        : "=l"(r) : "r"(__float_as_uint(x)), "r"(__float_as_uint(y)));
    return r;
}
__device__ __forceinline__ void fma2(unsigned long long& d,
                                     unsigned long long a,
                                     unsigned long long b) {
    asm("fma.rn.f32x2 %0, %1, %2, %3;" : "=l"(d) : "l"(a), "l"(b), "l"(d));
}
__device__ __forceinline__ float2 unpack2(unsigned long long v) {
    unsigned lo, hi;
    asm("mov.b64 {%0, %1}, %2;" : "=r"(lo), "=r"(hi) : "l"(v));
    return make_float2(__uint_as_float(lo), __uint_as_float(hi));
}

// ---------------- scratch (device globals; no allocation) ----------------
__device__ float g_h[BB * TT * HH];
__device__ float g_seq[BB * TT * HH];
__device__ float g_xg[BB * TT * G4];
__device__ float g_hA[BB * HH], g_hB[BB * HH];
__device__ float g_ln[BB * HH];
__device__ float g_d2[BB * (HH / 2)];
__device__ unsigned g_bar_count = 0;
__device__ unsigned g_bar_gen = 0;

// ---------------- software grid barrier ----------------
__device__ __forceinline__ void grid_bar() {
    __syncthreads();
    if (threadIdx.x == 0) {
        __threadfence();
        unsigned gen = *((volatile unsigned*)&g_bar_gen);
        if (atomicAdd(&g_bar_count, 1u) == NBLK - 1) {
            g_bar_count = 0;
            __threadfence();
            atomicAdd(&g_bar_gen, 1u);
        } else {
            while (*((volatile unsigned*)&g_bar_gen) == gen) {}
            __threadfence();
        }
    }
    __syncthreads();
}

// ---------------- dense1 + spectral-norm scale ----------------
__global__ void dense1_norm(const float* __restrict__ x,
                            const float* __restrict__ W1,
                            const float* __restrict__ b1) {
    __shared__ float xs[16][FF];
    __shared__ float hs[16][HH];
    const int tid = threadIdx.x;
    const int m0 = blockIdx.x * 16;

    for (int i = tid; i < 16 * FF; i += 256) {
        int r = i / FF, k = i % FF;
        xs[r][k] = x[(m0 + r) * FF + k];
    }
    __syncthreads();

    const int c0 = tid * 2;
    float acc0[16], acc1[16];
#pragma unroll
    for (int r = 0; r < 16; r++) { acc0[r] = 0.f; acc1[r] = 0.f; }

    for (int k = 0; k < FF; k++) {
        float w0 = W1[k * HH + c0];
        float w1 = W1[k * HH + c0 + 1];
#pragma unroll
        for (int r = 0; r < 16; r++) {
            float xv = xs[r][k];
            acc0[r] += xv * w0;
            acc1[r] += xv * w1;
        }
    }
    float bb0 = b1[c0], bb1 = b1[c0 + 1];
#pragma unroll
    for (int r = 0; r < 16; r++) {
        hs[r][c0]     = acc0[r] + bb0;
        hs[r][c0 + 1] = acc1[r] + bb1;
    }
    __syncthreads();

    int wid = tid >> 5, lane = tid & 31;
#pragma unroll
    for (int rr = 0; rr < 2; rr++) {
        int r = wid * 2 + rr;
        float ss = 0.f;
        for (int c = lane; c < HH; c += 32) { float v = hs[r][c]; ss += v * v; }
#pragma unroll
        for (int o = 16; o; o >>= 1) ss += __shfl_xor_sync(0xffffffffu, ss, o);
        float scale = sqrtf((float)HH) / fmaxf(sqrtf(ss), 1e-12f);
        for (int c = lane; c < HH; c += 32)
            g_h[(m0 + r) * HH + c] = hs[r][c] * scale;
    }
}

// ---------------- xg GEMM (f32x2, double-buffered regs) ----------------
// 128x128 tile, 256 threads, 8x8 per-thread tile as 4 row-pairs x 8 cols
__global__ void __launch_bounds__(256) gemm_xg(int src,
                                               const float* __restrict__ Wx,
                                               const float* __restrict__ bias) {
    const float* __restrict__ A = src ? g_seq : g_h;
    __shared__ float As[16 * 128];  // [k][m]
    __shared__ float Bs[16 * 128];  // [k][n]
    const int tid = threadIdx.x;
    const int tx = tid & 15, ty = tid >> 4;
    const int n0 = blockIdx.x * 128;
    const int m0 = blockIdx.y * 128;

    const int lm = tid >> 1;            // 0..127
    const int lk = (tid & 1) * 8;       // 0 or 8
    const int bn = (tid & 31) * 4;      // 0..124
    const int bk = tid >> 5;            // 0..7

    unsigned long long acc[4][8];
#pragma unroll
    for (int i = 0; i < 4; i++)
#pragma unroll
        for (int j = 0; j < 8; j++) acc[i][j] = 0ull;

    // initial prefetch (kc = 0)
    float4 ra0 = *(const float4*)&A[(m0 + lm) * HH + lk];
    float4 ra1 = *(const float4*)&A[(m0 + lm) * HH + lk + 4];
    float4 rb0 = *(const float4*)&Wx[bk * G4 + n0 + bn];
    float4 rb1 = *(const float4*)&Wx[(bk + 8) * G4 + n0 + bn];

    for (int kc = 0; kc < HH; kc += 16) {
        As[(lk + 0) * 128 + lm] = ra0.x;
        As[(lk + 1) * 128 + lm] = ra0.y;
        As[(lk + 2) * 128 + lm] = ra0.z;
        As[(lk + 3) * 128 + lm] = ra0.w;
        As[(lk + 4) * 128 + lm] = ra1.x;
        As[(lk + 5) * 128 + lm] = ra1.y;
        As[(lk + 6) * 128 + lm] = ra1.z;
        As[(lk + 7) * 128 + lm] = ra1.w;
        *(float4*)&Bs[bk * 128 + bn] = rb0;
        *(float4*)&Bs[(bk + 8) * 128 + bn] = rb1;
        __syncthreads();

        if (kc + 16 < HH) {
            ra0 = *(const float4*)&A[(m0 + lm) * HH + kc + 16 + lk];
            ra1 = *(const float4*)&A[(m0 + lm) * HH + kc + 16 + lk + 4];
            rb0 = *(const float4*)&Wx[(kc + 16 + bk) * G4 + n0 + bn];
            rb1 = *(const float4*)&Wx[(kc + 16 + bk + 8) * G4 + n0 + bn];
        }

#pragma unroll
        for (int k = 0; k < 16; k++) {
            // row pairs come packed straight out of SMEM
            ulonglong2 pa01 = *(const ulonglong2*)&As[k * 128 + ty * 4];
            ulonglong2 pa23 = *(const ulonglong2*)&As[k * 128 + ty * 4 + 64];
            float4 b0 = *(const float4*)&Bs[k * 128 + tx * 4];
            float4 b1 = *(const float4*)&Bs[k * 128 + tx * 4 + 64];
            unsigned long long pb[8];
            pb[0] = pack2(b0.x, b0.x); pb[1] = pack2(b0.y, b0.y);
            pb[2] = pack2(b0.z, b0.z); pb[3] = pack2(b0.w, b0.w);
            pb[4] = pack2(b1.x, b1.x); pb[5] = pack2(b1.y, b1.y);
            pb[6] = pack2(b1.z, b1.z); pb[7] = pack2(b1.w, b1.w);
            unsigned long long pa[4] = {pa01.x, pa01.y, pa23.x, pa23.y};
#pragma unroll
            for (int i = 0; i < 4; i++)
#pragma unroll
                for (int j = 0; j < 8; j++) fma2(acc[i][j], pa[i], pb[j]);
        }
        __syncthreads();
    }

    float4 bia0 = *(const float4*)&bias[n0 + tx * 4];
    float4 bia1 = *(const float4*)&bias[n0 + tx * 4 + 64];
    float bl[8] = {bia0.x, bia0.y, bia0.z, bia0.w, bia1.x, bia1.y, bia1.z, bia1.w};

#pragma unroll
    for (int ip = 0; ip < 4; ip++) {
        int rlo = m0 + (ip >> 1) * 64 + ty * 4 + (ip & 1) * 2;
        int rhi = rlo + 1;
        float lo[8], hi[8];
#pragma unroll
        for (int j = 0; j < 8; j++) {
            float2 v = unpack2(acc[ip][j]);
            lo[j] = v.x + bl[j];
            hi[j] = v.y + bl[j];
        }
        *(float4*)&g_xg[(size_t)rlo * G4 + n0 + tx * 4] =
            make_float4(lo[0], lo[1], lo[2], lo[3]);
        *(float4*)&g_xg[(size_t)rlo * G4 + n0 + tx * 4 + 64] =
            make_float4(lo[4], lo[5], lo[6], lo[7]);
        *(float4*)&g_xg[(size_t)rhi * G4 + n0 + tx * 4] =
            make_float4(hi[0], hi[1], hi[2], hi[3]);
        *(float4*)&g_xg[(size_t)rhi * G4 + n0 + tx * 4 + 64] =
            make_float4(hi[4], hi[5], hi[6], hi[7]);
    }
}

// ---------------- zero initial LSTM hidden state ----------------
__global__ void zero_state() {
    int i = blockIdx.x * 256 + threadIdx.x;
    if (i < BB * HH) g_hA[i] = 0.f;
}

// ---------------- persistent fused LSTM (f32x2 inner loop) ----------------
#define SMEM_LSTM ((512 * 64 + 32 * 512 + 32 * 64 + 32 * 16) * 4)

__global__ void __launch_bounds__(256, 1)
lstm_persist(const float* __restrict__ Wh, int layer) {
    extern __shared__ float sm[];
    float* Whs = sm;                       // [512][64]
    float* As  = Whs + 512 * 64;           // [32][512]
    float* Gs  = As + 32 * 512;            // [32][64]
    float* cs  = Gs + 32 * 64;             // [32][16]

    const int tid = threadIdx.x;
    const int b0 = blockIdx.x * 32;
    const int j0 = blockIdx.y * 16;

    for (int i = tid; i < 512 * 64; i += 256) {
        int k = i >> 6, c = i & 63;
        Whs[i] = Wh[k * G4 + (c >> 4) * HH + j0 + (c & 15)];
    }
    for (int i = tid; i < 512; i += 256) cs[i] = 0.f;
    __syncthreads();

    const int c0 = (tid & 15) * 4;      // gate-col within 64
    const int r0 = (tid >> 4) * 2;      // batch row pair within 32

    for (int t = 0; t < TT; t++) {
        const float* __restrict__ hprev = (t & 1) ? g_hB : g_hA;
        float* __restrict__ hnext = (t & 1) ? g_hA : g_hB;

        for (int i = tid * 4; i < 32 * 512; i += 256 * 4)
            *(float4*)&As[i] =
                *(const float4*)&hprev[((b0 + (i >> 9)) << 9) + (i & 511)];
        __syncthreads();

        unsigned long long a00 = 0ull, a01 = 0ull, a10 = 0ull, a11 = 0ull;
        const float* A0 = &As[r0 * 512];
        const float* A1 = &As[(r0 + 1) * 512];
#pragma unroll 8
        for (int k = 0; k < 512; k++) {
            float v0 = A0[k], v1 = A1[k];
            unsigned long long pa0 = pack2(v0, v0);
            unsigned long long pa1 = pack2(v1, v1);
            ulonglong2 b2 = *(const ulonglong2*)&Whs[k * 64 + c0];
            fma2(a00, pa0, b2.x); fma2(a01, pa0, b2.y);
            fma2(a10, pa1, b2.x); fma2(a11, pa1, b2.y);
        }
        float2 u00 = unpack2(a00), u01 = unpack2(a01);
        float2 u10 = unpack2(a10), u11 = unpack2(a11);
        *(float4*)&Gs[r0 * 64 + c0]       = make_float4(u00.x, u00.y, u01.x, u01.y);
        *(float4*)&Gs[(r0 + 1) * 64 + c0] = make_float4(u10.x, u10.y, u11.x, u11.y);
        __syncthreads();

#pragma unroll
        for (int p = tid; p < 512; p += 256) {
            int rr = p >> 4, jj = p & 15;
            int b = b0 + rr, j = j0 + jj;
            const float* __restrict__ xg = &g_xg[(size_t)(b * TT + t) * G4 + j];
            float iv = Gs[rr * 64 + jj]      + xg[0];
            float fv = Gs[rr * 64 + 16 + jj] + xg[512];
            float cv = Gs[rr * 64 + 32 + jj] + xg[1024];
            float ov = Gs[rr * 64 + 48 + jj] + xg[1536];
            iv = 1.f / (1.f + __expf(-iv));
            fv = 1.f / (1.f + __expf(-fv));
            ov = 1.f / (1.f + __expf(-ov));
            cv = tanhf(cv);
            float c = fv * cs[p] + iv * cv;
            cs[p] = c;
            float h = ov * tanhf(c);
            hnext[b * HH + j] = h;
            if (layer == 0) g_seq[(size_t)(b * TT + t) * HH + j] = h;
        }

        if (t < TT - 1) grid_bar();
    }
}

// ---------------- layernorm (eps=1e-3) ----------------
__global__ void layernorm(const float* __restrict__ gamma,
                          const float* __restrict__ beta) {
    const int b = blockIdx.x, tid = threadIdx.x;
    const float* __restrict__ h = &g_hA[b * HH];
    __shared__ float red[8];
    __shared__ float bc_mu, bc_rs;

    float s = 0.f;
    for (int j = tid; j < HH; j += 256) s += h[j];
#pragma unroll
    for (int o = 16; o; o >>= 1) s += __shfl_xor_sync(0xffffffffu, s, o);
    if ((tid & 31) == 0) red[tid >> 5] = s;
    __syncthreads();
    if (tid == 0) {
        float tsum = 0.f;
        for (int i = 0; i < 8; i++) tsum += red[i];
        bc_mu = tsum / (float)HH;
    }
    __syncthreads();
    float mu = bc_mu;

    float v = 0.f;
    for (int j = tid; j < HH; j += 256) { float d = h[j] - mu; v += d * d; }
#pragma unroll
    for (int o = 16; o; o >>= 1) v += __shfl_xor_sync(0xffffffffu, v, o);
    __syncthreads();
    if ((tid & 31) == 0) red[tid >> 5] = v;
    __syncthreads();
    if (tid == 0) {
        float tsum = 0.f;
        for (int i = 0; i < 8; i++) tsum += red[i];
        bc_rs = rsqrtf(tsum / (float)HH + 1e-3f);
    }
    __syncthreads();
    float rs = bc_rs;

    for (int j = tid; j < HH; j += 256)
        g_ln[b * HH + j] = (h[j] - mu) * rs * gamma[j] + beta[j];
}

// ---------------- dense2 + relu ----------------
__global__ void dense2(const float* __restrict__ W2, const float* __restrict__ b2) {
    const int b = blockIdx.x, c = threadIdx.x;
    const float* __restrict__ h = &g_ln[b * HH];
    float s = b2[c];
    for (int k = 0; k < HH; k++) s += h[k] * W2[k * 256 + c];
    g_d2[b * 256 + c] = fmaxf(s, 0.f);
}

// ---------------- dense3 ----------------
__global__ void dense3(const float* __restrict__ W3, const float* __restrict__ b3,
                       float* __restrict__ out) {
    const int b = blockIdx.x, tid = threadIdx.x;
    float s = g_d2[b * 256 + tid] * W3[tid];
#pragma unroll
    for (int o = 16; o; o >>= 1) s += __shfl_xor_sync(0xffffffffu, s, o);
    __shared__ float red[8];
    if ((tid & 31) == 0) red[tid >> 5] = s;
    __syncthreads();
    if (tid == 0) {
        float tsum = 0.f;
        for (int i = 0; i < 8; i++) tsum += red[i];
        out[b] = tsum + b3[0];
    }
}

// ---------------- launch ----------------
extern "C" void kernel_launch(void* const* d_in, const int* in_sizes, int n_in,
                              void* d_out, int out_size) {
    const float* x     = (const float*)d_in[0];
    const float* W1    = (const float*)d_in[1];
    const float* b1    = (const float*)d_in[2];
    const float* Wx1   = (const float*)d_in[3];
    const float* Wh1   = (const float*)d_in[4];
    const float* bl1   = (const float*)d_in[5];
    const float* Wx2   = (const float*)d_in[6];
    const float* Wh2   = (const float*)d_in[7];
    const float* bl2   = (const float*)d_in[8];
    const float* gamma = (const float*)d_in[9];
    const float* beta  = (const float*)d_in[10];
    const float* W2    = (const float*)d_in[11];
    const float* b2    = (const float*)d_in[12];
    const float* W3    = (const float*)d_in[13];
    const float* b3    = (const float*)d_in[14];
    float* out = (float*)d_out;

    static int smem_set = 0;
    if (!smem_set) {
        cudaFuncSetAttribute(lstm_persist,
                             cudaFuncAttributeMaxDynamicSharedMemorySize,
                             SMEM_LSTM);
        smem_set = 1;
    }

    dense1_norm<<<(BB * TT) / 16, 256>>>(x, W1, b1);

    gemm_xg<<<dim3(G4 / 128, (BB * TT) / 128), 256>>>(0, Wx1, bl1);
    zero_state<<<(BB * HH + 255) / 256, 256>>>();
    lstm_persist<<<dim3(4, 32), 256, SMEM_LSTM>>>(Wh1, 0);

    gemm_xg<<<dim3(G4 / 128, (BB * TT) / 128), 256>>>(1, Wx2, bl2);
    zero_state<<<(BB * HH + 255) / 256, 256>>>();
    lstm_persist<<<dim3(4, 32), 256, SMEM_LSTM>>>(Wh2, 1);

    layernorm<<<BB, 256>>>(gamma, beta);
    dense2<<<BB, 256>>>(W2, b2);
    dense3<<<BB, 256>>>(W3, b3, out);
}